// round 8
// baseline (speedup 1.0000x reference)
#include <cuda_runtime.h>
#include <cstdint>
#include <cstddef>

// ---------------- problem constants (fixed by the dataset) ----------------
#define Bn     16
#define SEQn   256
#define DIMn   1024
#define HEADSn 16
#define DHEADn 64
#define INNERn 1024
#define Mmem   8
#define TXTn   77
#define KVn    (Mmem*SEQn + TXTn)   // 2125
#define MSn    (Mmem*SEQn)          // 2048
#define SCALEf 0.125f               // 64^-0.5

#define ROWS_X   (Bn*SEQn)          // 4096
#define ROWS_C   (Bn*KVn)           // 34000
#define BHn      (Bn*HEADSn)        // 256

// ---------------- scratch (device globals: no allocation allowed) ---------
__device__ float g_Q[ROWS_X * INNERn];
__device__ float g_K[ROWS_C * INNERn];
__device__ float g_V[ROWS_C * INNERn];
__device__ float g_O[ROWS_X * INNERn];
__device__ float g_Wt[4 * DIMn * INNERn];
__device__ float g_Xr[ROWS_X * DIMn];
__device__ float g_Cr[ROWS_C * DIMn];

// ---------------- helpers --------------------------------------------------
__device__ __forceinline__ uint32_t smem_u32(const void* p) {
    uint32_t a;
    asm("{ .reg .u64 t; cvta.to.shared.u64 t, %1; cvt.u32.u64 %0, t; }" : "=r"(a) : "l"(p));
    return a;
}
__device__ __forceinline__ float rna_tf32(float x) {
    float y;
    asm("cvt.rna.tf32.f32 %0, %1;" : "=f"(y) : "f"(x));
    return y;
}
#define MMA_TF32(d0,d1,d2,d3,a0,a1,a2,a3,b0,b1)                               \
    asm volatile(                                                             \
        "mma.sync.aligned.m16n8k8.row.col.f32.tf32.tf32.f32 "                 \
        "{%0,%1,%2,%3},{%4,%5,%6,%7},{%8,%9},{%0,%1,%2,%3};"                  \
        : "+f"(d0), "+f"(d1), "+f"(d2), "+f"(d3)                              \
        : "r"(a0), "r"(a1), "r"(a2), "r"(a3), "r"(b0), "r"(b1))
#define CP16(dst, src)     asm volatile("cp.async.cg.shared.global [%0], [%1], 16;" :: "r"(dst), "l"(src))
#define CP16P(dst, src, p) asm volatile("cp.async.cg.shared.global [%0], [%1], 16, %2;" :: "r"(dst), "l"(src), "r"(p))
#define CP_COMMIT()        asm volatile("cp.async.commit_group;" ::: "memory")
#define CP_WAIT(n)         asm volatile("cp.async.wait_group %0;" :: "n"(n) : "memory")

// =================== tf32 mma.sync GEMM (projections) ======================
// C[M,1024] = A[M,1024] @ Bt[n][k]^T   (Bt K-major, N = K = 1024 fixed)
// Tile 128x128x32, 256 thr, 8 warps 2x4, warp tile 64x32.
// 2-stage double buffer, R5-proven control flow: wait(1)/sync -> compute ->
// sync -> reissue same buffer.
#define GSTR 36                       // smem row stride (floats): bank-safe
#define GTILE (128*GSTR)              // one A or B tile (floats)
#define GSTG  (2*GTILE)               // per stage (A + B)
#define G_SMEM (2*GSTG*4)             // 73728 bytes

template<bool BIAS, bool RND>
__global__ __launch_bounds__(256, 2)
void gemm_mma(const float* __restrict__ A, const float* __restrict__ Bt,
              float* __restrict__ C, const float* __restrict__ bias, int M)
{
    extern __shared__ float smx[];

    const int tid  = threadIdx.x;
    const int wid  = tid >> 5, lane = tid & 31;
    const int g    = lane >> 2, tg = lane & 3;
    const int wm   = (wid >> 2) * 64;
    const int wn   = (wid & 3) * 32;
    const int m0   = blockIdx.y * 128, n0 = blockIdx.x * 128;

    float d[4][4][4];
#pragma unroll
    for (int i = 0; i < 4; i++)
#pragma unroll
        for (int j = 0; j < 4; j++)
#pragma unroll
            for (int q = 0; q < 4; q++) d[i][j][q] = 0.f;

    auto issue = [&](int stg, int kt) {
        const int k0 = kt * 32;
        float* sA = smx + stg * GSTG;
        float* sB = sA + GTILE;
#pragma unroll
        for (int e = 0; e < 4; e++) {
            int idx = tid + e * 256;        // 0..1023
            int row = idx >> 3, c4 = idx & 7;
            int ga = m0 + row;
            int pa = (ga < M) ? 16 : 0;
            if (ga >= M) ga = M - 1;
            uint32_t da = smem_u32(&sA[row * GSTR + c4 * 4]);
            CP16P(da, A + (size_t)ga * 1024u + k0 + c4 * 4, pa);
            uint32_t db = smem_u32(&sB[row * GSTR + c4 * 4]);
            CP16(db, Bt + (size_t)(n0 + row) * 1024u + k0 + c4 * 4);
        }
        CP_COMMIT();
    };

    issue(0, 0);
    issue(1, 1);

    for (int kt = 0; kt < 32; kt++) {
        const int buf = kt & 1;
        if (kt < 31) CP_WAIT(1);
        else         CP_WAIT(0);
        __syncthreads();

        const float* Ab = smx + buf * GSTG;
        const float* Bb = Ab + GTILE;
#pragma unroll
        for (int ks = 0; ks < 4; ks++) {
            uint32_t af[4][4], bf[4][2];
#pragma unroll
            for (int i = 0; i < 4; i++) {
                const float* base = &Ab[(wm + i * 16) * GSTR + ks * 8];
                af[i][0] = __float_as_uint(base[(g)     * GSTR + tg]);
                af[i][1] = __float_as_uint(base[(g + 8) * GSTR + tg]);
                af[i][2] = __float_as_uint(base[(g)     * GSTR + tg + 4]);
                af[i][3] = __float_as_uint(base[(g + 8) * GSTR + tg + 4]);
            }
#pragma unroll
            for (int j = 0; j < 4; j++) {
                const float* base = &Bb[(wn + j * 8 + g) * GSTR + ks * 8];
                bf[j][0] = __float_as_uint(base[tg]);
                bf[j][1] = __float_as_uint(base[tg + 4]);
            }
#pragma unroll
            for (int i = 0; i < 4; i++)
#pragma unroll
                for (int j = 0; j < 4; j++)
                    MMA_TF32(d[i][j][0], d[i][j][1], d[i][j][2], d[i][j][3],
                             af[i][0], af[i][1], af[i][2], af[i][3],
                             bf[j][0], bf[j][1]);
        }
        __syncthreads();
        if (kt + 2 < 32) issue(buf, kt + 2);
    }

#pragma unroll
    for (int i = 0; i < 4; i++) {
        const int r0 = m0 + wm + i * 16 + g;
#pragma unroll
        for (int j = 0; j < 4; j++) {
            const int c = n0 + wn + j * 8 + tg * 2;
            float2 v0 = make_float2(d[i][j][0], d[i][j][1]);
            float2 v1 = make_float2(d[i][j][2], d[i][j][3]);
            if (BIAS) {
                const float b0 = bias[c], b1 = bias[c + 1];
                v0.x += b0; v0.y += b1; v1.x += b0; v1.y += b1;
            }
            if (RND) {
                v0.x = rna_tf32(v0.x); v0.y = rna_tf32(v0.y);
                v1.x = rna_tf32(v1.x); v1.y = rna_tf32(v1.y);
            }
            if (r0 < M)     *(float2*)&C[(size_t)r0 * 1024u + c] = v0;
            if (r0 + 8 < M) *(float2*)&C[(size_t)(r0 + 8) * 1024u + c] = v1;
        }
    }
}

// =================== fused flash attention (tf32 mma) ======================
// One CTA per (m-tile of 128, b*h). Q in smem (pre-scaled, rna). KV chunks
// of 64, DOUBLE-BUFFERED: K+V of one chunk form ONE cp.async commit group;
// chunk t+2 is issued into buffer t%2 after the end-of-chunk barrier
// (identical control flow to the proven projection-GEMM pipeline).
#define QS_O  0                        // 128 x 68
#define KV_BUF 8960                    // K (64x68) + V (64x72) per buffer
#define K0_O  8704
#define V0_O  (K0_O + 64*68)           // 13056
#define SS_O  (K0_O + 2*KV_BUF)        // 26624, 128 x 68
#define MR_O  (SS_O + 128*68)          // 35328
#define LR_O  (MR_O + 128)
#define AR_O  (LR_O + 128)
#define FL_SMEM ((AR_O + 128) * 4)     // 142848 bytes

#define NCHUNK ((KVn + 63) / 64)       // 34

__global__ __launch_bounds__(256, 1)
void flash_attn(const float* __restrict__ Q, const float* __restrict__ K,
                const float* __restrict__ V, float* __restrict__ O)
{
    extern __shared__ float sm[];
    const int tid = threadIdx.x;
    const int wid = tid >> 5, lane = tid & 31;
    const int g = lane >> 2, tg = lane & 3;
    const int bh = blockIdx.y, b = bh >> 4, h = bh & 15;
    const int m0 = blockIdx.x * 128;

    const float* Qb = Q + ((size_t)(b * SEQn + m0)) * 1024u + h * 64;
    const float* Kb = K + ((size_t)b * KVn) * 1024u + h * 64;
    const float* Vb = V + ((size_t)b * KVn) * 1024u + h * 64;

    auto issue_kv = [&](int t, int pb) {
        const int kv0 = t * 64;
        const int ko = K0_O + pb * KV_BUF;
        const int vo = V0_O + pb * KV_BUF;
#pragma unroll
        for (int e = 0; e < 4; e++) {
            int idx = tid + e * 256;          // 0..1023
            int r = idx >> 4, c4 = idx & 15;
            int kvr = kv0 + r; if (kvr >= KVn) kvr = KVn - 1;
            uint32_t dk = smem_u32(&sm[ko + r * 68 + c4 * 4]);
            CP16(dk, Kb + (size_t)kvr * 1024u + c4 * 4);
            uint32_t dv = smem_u32(&sm[vo + r * 72 + c4 * 4]);
            CP16(dv, Vb + (size_t)kvr * 1024u + c4 * 4);
        }
        CP_COMMIT();
    };

    // prologue: chunks 0 and 1 in flight while Q tile is staged
    issue_kv(0, 0);
    issue_kv(1, 1);

    for (int e = tid; e < 128 * 64; e += 256) {
        int r = e >> 6, c = e & 63;
        sm[QS_O + r * 68 + c] = rna_tf32(Qb[(size_t)r * 1024u + c] * SCALEf);
    }
    if (tid < 128) { sm[MR_O + tid] = -1e30f; sm[LR_O + tid] = 0.f; }

    float oacc[4][2][4];
#pragma unroll
    for (int i = 0; i < 4; i++)
#pragma unroll
        for (int j = 0; j < 2; j++)
#pragma unroll
            for (int q = 0; q < 4; q++) oacc[i][j][q] = 0.f;

    const int om = (wid >> 2) * 64;   // warp m offset
    const int on = (wid & 3) * 16;    // warp n offset
    __syncthreads();

    for (int t = 0; t < NCHUNK; t++) {
        const int pb = t & 1;
        const int kv0 = t * 64;
        const int rows = (KVn - kv0 < 64) ? (KVn - kv0) : 64;
        const int ko = K0_O + pb * KV_BUF;
        const int vo = V0_O + pb * KV_BUF;

        // ---- wait chunk t ----
        if (t < NCHUNK - 1) CP_WAIT(1);
        else                CP_WAIT(0);
        __syncthreads();

        // ---- S = Qs @ Ks^T  (warp tile 64x16) ----
        float s[4][2][4];
#pragma unroll
        for (int i = 0; i < 4; i++)
#pragma unroll
            for (int j = 0; j < 2; j++)
#pragma unroll
                for (int q = 0; q < 4; q++) s[i][j][q] = 0.f;

#pragma unroll
        for (int ks = 0; ks < 8; ks++) {
            uint32_t af[4][4], bf[2][2];
#pragma unroll
            for (int i = 0; i < 4; i++) {
                const float* base = &sm[QS_O + (om + i * 16) * 68 + ks * 8];
                af[i][0] = __float_as_uint(base[(g)     * 68 + tg]);
                af[i][1] = __float_as_uint(base[(g + 8) * 68 + tg]);
                af[i][2] = __float_as_uint(base[(g)     * 68 + tg + 4]);
                af[i][3] = __float_as_uint(base[(g + 8) * 68 + tg + 4]);
            }
#pragma unroll
            for (int j = 0; j < 2; j++) {
                const float* base = &sm[ko + (on + j * 8 + g) * 68 + ks * 8];
                bf[j][0] = __float_as_uint(base[tg]);
                bf[j][1] = __float_as_uint(base[tg + 4]);
            }
#pragma unroll
            for (int i = 0; i < 4; i++)
#pragma unroll
                for (int j = 0; j < 2; j++)
                    MMA_TF32(s[i][j][0], s[i][j][1], s[i][j][2], s[i][j][3],
                             af[i][0], af[i][1], af[i][2], af[i][3],
                             bf[j][0], bf[j][1]);
        }
        // write S fragments to smem
#pragma unroll
        for (int i = 0; i < 4; i++) {
            const int r0 = om + i * 16 + g;
#pragma unroll
            for (int j = 0; j < 2; j++) {
                const int c = on + j * 8 + tg * 2;
                sm[SS_O + r0 * 68 + c]           = s[i][j][0];
                sm[SS_O + r0 * 68 + c + 1]       = s[i][j][1];
                sm[SS_O + (r0 + 8) * 68 + c]     = s[i][j][2];
                sm[SS_O + (r0 + 8) * 68 + c + 1] = s[i][j][3];
            }
        }
        __syncthreads();

        // ---- online softmax: warp handles rows [wid*16, wid*16+16) ----
#pragma unroll 4
        for (int rr = 0; rr < 16; rr++) {
            const int r = wid * 16 + rr;
            const int c0 = lane * 2;
            float v0 = (c0     < rows) ? sm[SS_O + r * 68 + c0]     : -1e30f;
            float v1 = (c0 + 1 < rows) ? sm[SS_O + r * 68 + c0 + 1] : -1e30f;
            float mx = fmaxf(v0, v1);
#pragma unroll
            for (int o = 16; o; o >>= 1) mx = fmaxf(mx, __shfl_xor_sync(~0u, mx, o));
            const float mold = sm[MR_O + r];
            const float mnew = fmaxf(mold, mx);
            float p0 = (c0     < rows) ? rna_tf32(__expf(v0 - mnew)) : 0.f;
            float p1 = (c0 + 1 < rows) ? rna_tf32(__expf(v1 - mnew)) : 0.f;
            sm[SS_O + r * 68 + c0]     = p0;
            sm[SS_O + r * 68 + c0 + 1] = p1;
            float ls = p0 + p1;
#pragma unroll
            for (int o = 16; o; o >>= 1) ls += __shfl_xor_sync(~0u, ls, o);
            if (lane == 0) {
                const float al = __expf(mold - mnew);
                sm[AR_O + r] = al;
                sm[LR_O + r] = sm[LR_O + r] * al + ls;
                sm[MR_O + r] = mnew;
            }
        }
        __syncthreads();

        // ---- rescale O accumulators ----
#pragma unroll
        for (int i = 0; i < 4; i++) {
            const float a0 = sm[AR_O + om + i * 16 + g];
            const float a1 = sm[AR_O + om + i * 16 + g + 8];
#pragma unroll
            for (int j = 0; j < 2; j++) {
                oacc[i][j][0] *= a0; oacc[i][j][1] *= a0;
                oacc[i][j][2] *= a1; oacc[i][j][3] *= a1;
            }
        }

        // ---- O += P @ V ----
#pragma unroll
        for (int ks = 0; ks < 8; ks++) {
            uint32_t af[4][4], bf[2][2];
#pragma unroll
            for (int i = 0; i < 4; i++) {
                const float* base = &sm[SS_O + (om + i * 16) * 68 + ks * 8];
                af[i][0] = __float_as_uint(base[(g)     * 68 + tg]);
                af[i][1] = __float_as_uint(base[(g + 8) * 68 + tg]);
                af[i][2] = __float_as_uint(base[(g)     * 68 + tg + 4]);
                af[i][3] = __float_as_uint(base[(g + 8) * 68 + tg + 4]);
            }
#pragma unroll
            for (int j = 0; j < 2; j++) {
                bf[j][0] = __float_as_uint(sm[vo + (ks * 8 + tg)     * 72 + on + j * 8 + g]);
                bf[j][1] = __float_as_uint(sm[vo + (ks * 8 + tg + 4) * 72 + on + j * 8 + g]);
            }
#pragma unroll
            for (int i = 0; i < 4; i++)
#pragma unroll
                for (int j = 0; j < 2; j++)
                    MMA_TF32(oacc[i][j][0], oacc[i][j][1], oacc[i][j][2], oacc[i][j][3],
                             af[i][0], af[i][1], af[i][2], af[i][3],
                             bf[j][0], bf[j][1]);
        }
        __syncthreads();   // chunk t buffers free

        // refill this buffer with chunk t+2 (overlaps chunk t+1 compute)
        if (t + 2 < NCHUNK) issue_kv(t + 2, pb);
    }

    // ---- epilogue: O / l, rna-round for out-projection ----
    float* Ob = O + ((size_t)(b * SEQn + m0)) * 1024u + h * 64;
#pragma unroll
    for (int i = 0; i < 4; i++) {
        const int r0 = om + i * 16 + g;
        const float li0 = 1.f / sm[LR_O + r0];
        const float li1 = 1.f / sm[LR_O + r0 + 8];
#pragma unroll
        for (int j = 0; j < 2; j++) {
            const int c = on + j * 8 + tg * 2;
            float2 v0 = make_float2(rna_tf32(oacc[i][j][0] * li0), rna_tf32(oacc[i][j][1] * li0));
            float2 v1 = make_float2(rna_tf32(oacc[i][j][2] * li1), rna_tf32(oacc[i][j][3] * li1));
            *(float2*)&Ob[(size_t)r0 * 1024u + c]       = v0;
            *(float2*)&Ob[(size_t)(r0 + 8) * 1024u + c] = v1;
        }
    }
}

// ---------------- weight transpose + tf32 round ---------------------------
__global__ void transpose_1024(const float* __restrict__ W, float* __restrict__ Wt)
{
    __shared__ float t[32][33];
    const int bx = blockIdx.x * 32, by = blockIdx.y * 32;
    const int tx = threadIdx.x, ty = threadIdx.y;
#pragma unroll
    for (int i = 0; i < 4; i++)
        t[ty + i * 8][tx] = W[(size_t)(by + ty + i * 8) * 1024 + bx + tx];
    __syncthreads();
#pragma unroll
    for (int i = 0; i < 4; i++)
        Wt[(size_t)(bx + ty + i * 8) * 1024 + by + tx] = rna_tf32(t[tx][ty + i * 8]);
}

// ---------------- tf32 rounding copy ---------------------------------------
__global__ void round_copy(const float4* __restrict__ in, float4* __restrict__ out, int n4)
{
    int i = blockIdx.x * blockDim.x + threadIdx.x;
    if (i < n4) {
        float4 v = in[i];
        v.x = rna_tf32(v.x); v.y = rna_tf32(v.y);
        v.z = rna_tf32(v.z); v.w = rna_tf32(v.w);
        out[i] = v;
    }
}

// ---------------- rotary on Q ---------------------------------------------
__global__ void rotary_q_kernel(float* __restrict__ Q, const float* __restrict__ freqs,
                                const int* __restrict__ cur)
{
    const int row = blockIdx.x;
    const int s   = row % SEQn;
    const int p   = threadIdx.x;
    const int col0 = 2*p;
    const int d0   = col0 & 63;

    const int cp = cur[0];
    const int inner = cp % 16;
    const int rs = inner % 4, cs = inner / 4;
    const int fr = rs*16 + (s >> 4), fc = cs*16 + (s & 15);
    const float* f = freqs + ((fr<<6) + fc) * 64;
    const float f0 = f[d0], f1 = f[d0+1];

    float* q = Q + (long long)row*INNERn + col0;
    const float t0 = q[0], t1 = q[1];
    q[0] = t0*cosf(f0) - t1*sinf(f0);
    q[1] = t1*cosf(f1) + t0*sinf(f1);
}

// ---------------- bias + rotary on memory K rows ---------------------------
__global__ void biasrot_k_kernel(float* __restrict__ K, const float* __restrict__ freqs,
                                 const float* __restrict__ rel_table,
                                 const int* __restrict__ memidx,
                                 const int* __restrict__ cur)
{
    const int gid = blockIdx.x;
    const int b = gid / MSn;
    const int j = gid - b*MSn;
    const int m = j >> 8;
    const int jj = j & 255;

    const int p = threadIdx.x;
    const int col0 = 2*p;
    const int h  = col0 >> 6;
    const int d0 = col0 & 63;

    const int cp = cur[0];
    const int ci = cp % 16;
    const int rs = ci % 4, cs = ci / 4, ts = cp / 16;
    const int mi = memidx[m];
    const int mn = mi % 16;
    const int rt = mn % 4, ct = mn / 4, tt = mi / 16;
    const int rel = (rt - rs + 4)*9 + (ct - cs + 4) + (tt - ts + 4)*81;
    const float bias = rel_table[rel*HEADSn + h];

    const int fr = rt*16 + (jj >> 4), fc = ct*16 + (jj & 15);
    const float* f = freqs + ((fr<<6) + fc) * 64;
    const float f0 = f[d0], f1 = f[d0+1];

    float* kp = K + ((long long)b*KVn + j)*INNERn + col0;
    const float t0 = kp[0] + bias, t1 = kp[1] + bias;
    kp[0] = t0*cosf(f0) - t1*sinf(f0);
    kp[1] = t1*cosf(f1) + t0*sinf(f1);
}

// ---------------- host launch ----------------------------------------------
extern "C" void kernel_launch(void* const* d_in, const int* in_sizes, int n_in,
                              void* d_out, int out_size)
{
    const float* x     = (const float*)d_in[0];
    const float* cond  = (const float*)d_in[1];
    const float* freqs = (const float*)d_in[2];
    const float* Wq    = (const float*)d_in[3];
    const float* Wk    = (const float*)d_in[4];
    const float* Wv    = (const float*)d_in[5];
    const float* rel   = (const float*)d_in[6];
    const float* Wo    = (const float*)d_in[7];
    const float* bo    = (const float*)d_in[8];
    const int*   memi  = (const int*)d_in[9];
    const int*   cur   = (const int*)d_in[10];
    float* out = (float*)d_out;

    float *Qb, *Kb, *Vb, *Ob, *Wt, *Xr, *Cr;
    cudaGetSymbolAddress((void**)&Qb, g_Q);
    cudaGetSymbolAddress((void**)&Kb, g_K);
    cudaGetSymbolAddress((void**)&Vb, g_V);
    cudaGetSymbolAddress((void**)&Ob, g_O);
    cudaGetSymbolAddress((void**)&Wt, g_Wt);
    cudaGetSymbolAddress((void**)&Xr, g_Xr);
    cudaGetSymbolAddress((void**)&Cr, g_Cr);

    cudaFuncSetAttribute(flash_attn, cudaFuncAttributeMaxDynamicSharedMemorySize, FL_SMEM);
    cudaFuncSetAttribute(gemm_mma<false,false>, cudaFuncAttributeMaxDynamicSharedMemorySize, G_SMEM);
    cudaFuncSetAttribute(gemm_mma<false,true >, cudaFuncAttributeMaxDynamicSharedMemorySize, G_SMEM);
    cudaFuncSetAttribute(gemm_mma<true, false>, cudaFuncAttributeMaxDynamicSharedMemorySize, G_SMEM);

    float* Wtq = Wt + 0LL * DIMn * INNERn;
    float* Wtk = Wt + 1LL * DIMn * INNERn;
    float* Wtv = Wt + 2LL * DIMn * INNERn;
    float* Wto = Wt + 3LL * DIMn * INNERn;

    // 0) tf32-round activations; transpose+round weights to K-major [N][K]
    round_copy<<<(ROWS_X*DIMn/4 + 255)/256, 256>>>((const float4*)x,    (float4*)Xr, ROWS_X*DIMn/4);
    round_copy<<<(ROWS_C*DIMn/4 + 255)/256, 256>>>((const float4*)cond, (float4*)Cr, ROWS_C*DIMn/4);
    transpose_1024<<<dim3(32,32), dim3(32,8)>>>(Wq, Wtq);
    transpose_1024<<<dim3(32,32), dim3(32,8)>>>(Wk, Wtk);
    transpose_1024<<<dim3(32,32), dim3(32,8)>>>(Wv, Wtv);
    transpose_1024<<<dim3(32,32), dim3(32,8)>>>(Wo, Wto);

    // 1-3) projections on tf32 tensor cores (V rna-rounded for PV mma)
    gemm_mma<false,false><<<dim3(8, 32),  256, G_SMEM>>>(Xr, Wtq, Qb, nullptr, ROWS_X);
    gemm_mma<false,false><<<dim3(8, 266), 256, G_SMEM>>>(Cr, Wtk, Kb, nullptr, ROWS_C);
    gemm_mma<false,true ><<<dim3(8, 266), 256, G_SMEM>>>(Cr, Wtv, Vb, nullptr, ROWS_C);

    // 4) rotary(Q)
    rotary_q_kernel<<<ROWS_X, 512>>>(Qb, freqs, cur);

    // 5) bias + rotary on memory K rows
    biasrot_k_kernel<<<Bn*MSn, 512>>>(Kb, freqs, rel, memi, cur);

    // 6-8) fused flash attention (tf32 mma, online softmax), writes rna(O)
    flash_attn<<<dim3(2, BHn), 256, FL_SMEM>>>(Qb, Kb, Vb, Ob);

    // 9) out = O @ Wo + bo  (tf32 tensor cores, bias epilogue)
    gemm_mma<true,false><<<dim3(8, 32), 256, G_SMEM>>>(Ob, Wto, out, bo, ROWS_X);
}

// round 9
// speedup vs baseline: 1.1089x; 1.1089x over previous
#include <cuda_runtime.h>
#include <cstdint>
#include <cstddef>

// ---------------- problem constants (fixed by the dataset) ----------------
#define Bn     16
#define SEQn   256
#define DIMn   1024
#define HEADSn 16
#define DHEADn 64
#define INNERn 1024
#define Mmem   8
#define TXTn   77
#define KVn    (Mmem*SEQn + TXTn)   // 2125
#define MSn    (Mmem*SEQn)          // 2048
#define SCALEf 0.125f               // 64^-0.5

#define ROWS_X   (Bn*SEQn)          // 4096
#define ROWS_C   (Bn*KVn)           // 34000
#define BHn      (Bn*HEADSn)        // 256

// ---------------- scratch (device globals: no allocation allowed) ---------
__device__ float g_Q[ROWS_X * INNERn];
__device__ float g_K[ROWS_C * INNERn];
__device__ float g_V[ROWS_C * INNERn];
__device__ float g_O[ROWS_X * INNERn];
__device__ float g_Wt[4 * DIMn * INNERn];
__device__ float g_Xr[ROWS_X * DIMn];
__device__ float g_Cr[ROWS_C * DIMn];

// ---------------- helpers --------------------------------------------------
__device__ __forceinline__ uint32_t smem_u32(const void* p) {
    uint32_t a;
    asm("{ .reg .u64 t; cvta.to.shared.u64 t, %1; cvt.u32.u64 %0, t; }" : "=r"(a) : "l"(p));
    return a;
}
__device__ __forceinline__ float rna_tf32(float x) {
    float y;
    asm("cvt.rna.tf32.f32 %0, %1;" : "=f"(y) : "f"(x));
    return y;
}
#define MMA_TF32(d0,d1,d2,d3,a0,a1,a2,a3,b0,b1)                               \
    asm volatile(                                                             \
        "mma.sync.aligned.m16n8k8.row.col.f32.tf32.tf32.f32 "                 \
        "{%0,%1,%2,%3},{%4,%5,%6,%7},{%8,%9},{%0,%1,%2,%3};"                  \
        : "+f"(d0), "+f"(d1), "+f"(d2), "+f"(d3)                              \
        : "r"(a0), "r"(a1), "r"(a2), "r"(a3), "r"(b0), "r"(b1))
#define CP16(dst, src)     asm volatile("cp.async.cg.shared.global [%0], [%1], 16;" :: "r"(dst), "l"(src))
#define CP16P(dst, src, p) asm volatile("cp.async.cg.shared.global [%0], [%1], 16, %2;" :: "r"(dst), "l"(src), "r"(p))
#define CP_COMMIT()        asm volatile("cp.async.commit_group;" ::: "memory")
#define CP_WAIT(n)         asm volatile("cp.async.wait_group %0;" :: "n"(n) : "memory")

// =================== tf32 mma.sync GEMM (projections) ======================
// C[M,1024] = A[M,1024] @ Bt[n][k]^T   (Bt K-major, N = K = 1024 fixed)
// Tile 128x128x16, 128 threads, 4 warps in 2x2, WARP TILE 64x64.
// R5-proven 2-stage double-buffer control flow.
#define SA_STR 20   // smem row stride in floats (bank-conflict-free)

template<bool BIAS, bool RND>
__global__ __launch_bounds__(128, 2)
void gemm_mma(const float* __restrict__ A, const float* __restrict__ Bt,
              float* __restrict__ C, const float* __restrict__ bias, int M)
{
    __shared__ float As[2][128 * SA_STR];
    __shared__ float Bs[2][128 * SA_STR];

    const int tid  = threadIdx.x;
    const int wid  = tid >> 5, lane = tid & 31;
    const int g    = lane >> 2, tg = lane & 3;
    const int wm   = (wid >> 1) * 64;   // warp m offset (0 or 64)
    const int wn   = (wid & 1) * 64;    // warp n offset (0 or 64)
    const int m0   = blockIdx.y * 128, n0 = blockIdx.x * 128;

    float d[4][8][4];
#pragma unroll
    for (int i = 0; i < 4; i++)
#pragma unroll
        for (int j = 0; j < 8; j++)
#pragma unroll
            for (int q = 0; q < 4; q++) d[i][j][q] = 0.f;

    auto issue = [&](int buf, int kt) {
        const int k0 = kt * 16;
#pragma unroll
        for (int e = 0; e < 4; e++) {
            int idx = tid + e * 128;        // 0..511
            int row = idx >> 2, c4 = idx & 3;
            int ga = m0 + row;
            int pa = (ga < M) ? 16 : 0;
            if (ga >= M) ga = M - 1;
            uint32_t da = smem_u32(&As[buf][row * SA_STR + c4 * 4]);
            CP16P(da, A + (size_t)ga * 1024u + k0 + c4 * 4, pa);
            uint32_t db = smem_u32(&Bs[buf][row * SA_STR + c4 * 4]);
            CP16(db, Bt + (size_t)(n0 + row) * 1024u + k0 + c4 * 4);
        }
        CP_COMMIT();
    };

    issue(0, 0);
    issue(1, 1);

    for (int kt = 0; kt < 64; kt++) {
        const int buf = kt & 1;
        if (kt < 63) CP_WAIT(1);
        else         CP_WAIT(0);
        __syncthreads();

#pragma unroll
        for (int ks = 0; ks < 2; ks++) {
            uint32_t af[4][4], bf[8][2];
#pragma unroll
            for (int i = 0; i < 4; i++) {
                const float* base = &As[buf][(wm + i * 16) * SA_STR + ks * 8];
                af[i][0] = __float_as_uint(base[(g)     * SA_STR + tg]);
                af[i][1] = __float_as_uint(base[(g + 8) * SA_STR + tg]);
                af[i][2] = __float_as_uint(base[(g)     * SA_STR + tg + 4]);
                af[i][3] = __float_as_uint(base[(g + 8) * SA_STR + tg + 4]);
            }
#pragma unroll
            for (int j = 0; j < 8; j++) {
                const float* base = &Bs[buf][(wn + j * 8 + g) * SA_STR + ks * 8];
                bf[j][0] = __float_as_uint(base[tg]);
                bf[j][1] = __float_as_uint(base[tg + 4]);
            }
#pragma unroll
            for (int i = 0; i < 4; i++)
#pragma unroll
                for (int j = 0; j < 8; j++)
                    MMA_TF32(d[i][j][0], d[i][j][1], d[i][j][2], d[i][j][3],
                             af[i][0], af[i][1], af[i][2], af[i][3],
                             bf[j][0], bf[j][1]);
        }
        __syncthreads();
        if (kt + 2 < 64) issue(buf, kt + 2);
    }

    // epilogue: warp writes 64x64
#pragma unroll
    for (int i = 0; i < 4; i++) {
        const int r0 = m0 + wm + i * 16 + g;
#pragma unroll
        for (int j = 0; j < 8; j++) {
            const int c = n0 + wn + j * 8 + tg * 2;
            float2 v0 = make_float2(d[i][j][0], d[i][j][1]);
            float2 v1 = make_float2(d[i][j][2], d[i][j][3]);
            if (BIAS) {
                const float b0 = bias[c], b1 = bias[c + 1];
                v0.x += b0; v0.y += b1; v1.x += b0; v1.y += b1;
            }
            if (RND) {
                v0.x = rna_tf32(v0.x); v0.y = rna_tf32(v0.y);
                v1.x = rna_tf32(v1.x); v1.y = rna_tf32(v1.y);
            }
            if (r0 < M)     *(float2*)&C[(size_t)r0 * 1024u + c] = v0;
            if (r0 + 8 < M) *(float2*)&C[(size_t)(r0 + 8) * 1024u + c] = v1;
        }
    }
}

// =================== fused flash attention (tf32 mma) ======================
// EXACT R5 version (passed at 2062us): occ 2, per-chunk K+V load then wait(0).
#define QS_O 0                        // 128 x 68
#define KS_O (QS_O + 128*68)          // 64 x 68
#define VS_O (KS_O + 64*68)           // 64 x 72
#define SS_O (VS_O + 64*72)           // 128 x 68
#define MR_O (SS_O + 128*68)          // 128
#define LR_O (MR_O + 128)             // 128
#define AR_O (LR_O + 128)             // 128
#define FL_SMEM ((AR_O + 128) * 4)    // bytes = 107008

#define NCHUNK ((KVn + 63) / 64)      // 34

__global__ __launch_bounds__(256, 2)
void flash_attn(const float* __restrict__ Q, const float* __restrict__ K,
                const float* __restrict__ V, float* __restrict__ O)
{
    extern __shared__ float sm[];
    const int tid = threadIdx.x;
    const int wid = tid >> 5, lane = tid & 31;
    const int g = lane >> 2, tg = lane & 3;
    const int bh = blockIdx.y, b = bh >> 4, h = bh & 15;
    const int m0 = blockIdx.x * 128;

    const float* Qb = Q + ((size_t)(b * SEQn + m0)) * 1024u + h * 64;
    const float* Kb = K + ((size_t)b * KVn) * 1024u + h * 64;
    const float* Vb = V + ((size_t)b * KVn) * 1024u + h * 64;

    // Q tile: pre-scale + rna-round
    for (int e = tid; e < 128 * 64; e += 256) {
        int r = e >> 6, c = e & 63;
        sm[QS_O + r * 68 + c] = rna_tf32(Qb[(size_t)r * 1024u + c] * SCALEf);
    }
    if (tid < 128) { sm[MR_O + tid] = -1e30f; sm[LR_O + tid] = 0.f; }

    float oacc[4][2][4];
#pragma unroll
    for (int i = 0; i < 4; i++)
#pragma unroll
        for (int j = 0; j < 2; j++)
#pragma unroll
            for (int q = 0; q < 4; q++) oacc[i][j][q] = 0.f;

    const int om = (wid >> 2) * 64;   // warp m offset
    const int on = (wid & 3) * 16;    // warp n offset
    __syncthreads();

    for (int t = 0; t < NCHUNK; t++) {
        const int kv0 = t * 64;
        const int rows = (KVn - kv0 < 64) ? (KVn - kv0) : 64;

        // ---- load K,V chunk (64 x 64 f32 each) via cp.async ----
#pragma unroll
        for (int e = 0; e < 4; e++) {
            int idx = tid + e * 256;          // 0..1023
            int r = idx >> 4, c4 = idx & 15;
            int kvr = kv0 + r; if (kvr >= KVn) kvr = KVn - 1;
            const float* sk = Kb + (size_t)kvr * 1024u + c4 * 4;
            uint32_t dk = smem_u32(&sm[KS_O + r * 68 + c4 * 4]);
            CP16(dk, sk);
            const float* sv = Vb + (size_t)kvr * 1024u + c4 * 4;
            uint32_t dv = smem_u32(&sm[VS_O + r * 72 + c4 * 4]);
            CP16(dv, sv);
        }
        CP_COMMIT();
        CP_WAIT(0);
        __syncthreads();

        // ---- S = Qs @ Ks^T  (warp tile 64x16) ----
        float s[4][2][4];
#pragma unroll
        for (int i = 0; i < 4; i++)
#pragma unroll
            for (int j = 0; j < 2; j++)
#pragma unroll
                for (int q = 0; q < 4; q++) s[i][j][q] = 0.f;

#pragma unroll
        for (int ks = 0; ks < 8; ks++) {
            uint32_t af[4][4], bf[2][2];
#pragma unroll
            for (int i = 0; i < 4; i++) {
                const float* base = &sm[QS_O + (om + i * 16) * 68 + ks * 8];
                af[i][0] = __float_as_uint(base[(g)     * 68 + tg]);
                af[i][1] = __float_as_uint(base[(g + 8) * 68 + tg]);
                af[i][2] = __float_as_uint(base[(g)     * 68 + tg + 4]);
                af[i][3] = __float_as_uint(base[(g + 8) * 68 + tg + 4]);
            }
#pragma unroll
            for (int j = 0; j < 2; j++) {
                const float* base = &sm[KS_O + (on + j * 8 + g) * 68 + ks * 8];
                bf[j][0] = __float_as_uint(base[tg]);
                bf[j][1] = __float_as_uint(base[tg + 4]);
            }
#pragma unroll
            for (int i = 0; i < 4; i++)
#pragma unroll
                for (int j = 0; j < 2; j++)
                    MMA_TF32(s[i][j][0], s[i][j][1], s[i][j][2], s[i][j][3],
                             af[i][0], af[i][1], af[i][2], af[i][3],
                             bf[j][0], bf[j][1]);
        }
        // write S fragments to smem
#pragma unroll
        for (int i = 0; i < 4; i++) {
            const int r0 = om + i * 16 + g;
#pragma unroll
            for (int j = 0; j < 2; j++) {
                const int c = on + j * 8 + tg * 2;
                sm[SS_O + r0 * 68 + c]           = s[i][j][0];
                sm[SS_O + r0 * 68 + c + 1]       = s[i][j][1];
                sm[SS_O + (r0 + 8) * 68 + c]     = s[i][j][2];
                sm[SS_O + (r0 + 8) * 68 + c + 1] = s[i][j][3];
            }
        }
        __syncthreads();

        // ---- online softmax: warp handles rows [wid*16, wid*16+16) ----
#pragma unroll 4
        for (int rr = 0; rr < 16; rr++) {
            const int r = wid * 16 + rr;
            const int c0 = lane * 2;
            float v0 = (c0     < rows) ? sm[SS_O + r * 68 + c0]     : -1e30f;
            float v1 = (c0 + 1 < rows) ? sm[SS_O + r * 68 + c0 + 1] : -1e30f;
            float mx = fmaxf(v0, v1);
#pragma unroll
            for (int o = 16; o; o >>= 1) mx = fmaxf(mx, __shfl_xor_sync(~0u, mx, o));
            const float mold = sm[MR_O + r];
            const float mnew = fmaxf(mold, mx);
            float p0 = (c0     < rows) ? rna_tf32(__expf(v0 - mnew)) : 0.f;
            float p1 = (c0 + 1 < rows) ? rna_tf32(__expf(v1 - mnew)) : 0.f;
            sm[SS_O + r * 68 + c0]     = p0;
            sm[SS_O + r * 68 + c0 + 1] = p1;
            float ls = p0 + p1;
#pragma unroll
            for (int o = 16; o; o >>= 1) ls += __shfl_xor_sync(~0u, ls, o);
            if (lane == 0) {
                const float al = __expf(mold - mnew);
                sm[AR_O + r] = al;
                sm[LR_O + r] = sm[LR_O + r] * al + ls;
                sm[MR_O + r] = mnew;
            }
        }
        __syncthreads();

        // ---- rescale O accumulators ----
#pragma unroll
        for (int i = 0; i < 4; i++) {
            const float a0 = sm[AR_O + om + i * 16 + g];
            const float a1 = sm[AR_O + om + i * 16 + g + 8];
#pragma unroll
            for (int j = 0; j < 2; j++) {
                oacc[i][j][0] *= a0; oacc[i][j][1] *= a0;
                oacc[i][j][2] *= a1; oacc[i][j][3] *= a1;
            }
        }

        // ---- O += P @ V ----
#pragma unroll
        for (int ks = 0; ks < 8; ks++) {
            uint32_t af[4][4], bf[2][2];
#pragma unroll
            for (int i = 0; i < 4; i++) {
                const float* base = &sm[SS_O + (om + i * 16) * 68 + ks * 8];
                af[i][0] = __float_as_uint(base[(g)     * 68 + tg]);
                af[i][1] = __float_as_uint(base[(g + 8) * 68 + tg]);
                af[i][2] = __float_as_uint(base[(g)     * 68 + tg + 4]);
                af[i][3] = __float_as_uint(base[(g + 8) * 68 + tg + 4]);
            }
#pragma unroll
            for (int j = 0; j < 2; j++) {
                bf[j][0] = __float_as_uint(sm[VS_O + (ks * 8 + tg)     * 72 + on + j * 8 + g]);
                bf[j][1] = __float_as_uint(sm[VS_O + (ks * 8 + tg + 4) * 72 + on + j * 8 + g]);
            }
#pragma unroll
            for (int i = 0; i < 4; i++)
#pragma unroll
                for (int j = 0; j < 2; j++)
                    MMA_TF32(oacc[i][j][0], oacc[i][j][1], oacc[i][j][2], oacc[i][j][3],
                             af[i][0], af[i][1], af[i][2], af[i][3],
                             bf[j][0], bf[j][1]);
        }
        __syncthreads();
    }

    // ---- epilogue: O / l, rna-round for out-projection ----
    float* Ob = O + ((size_t)(b * SEQn + m0)) * 1024u + h * 64;
#pragma unroll
    for (int i = 0; i < 4; i++) {
        const int r0 = om + i * 16 + g;
        const float li0 = 1.f / sm[LR_O + r0];
        const float li1 = 1.f / sm[LR_O + r0 + 8];
#pragma unroll
        for (int j = 0; j < 2; j++) {
            const int c = on + j * 8 + tg * 2;
            float2 v0 = make_float2(rna_tf32(oacc[i][j][0] * li0), rna_tf32(oacc[i][j][1] * li0));
            float2 v1 = make_float2(rna_tf32(oacc[i][j][2] * li1), rna_tf32(oacc[i][j][3] * li1));
            *(float2*)&Ob[(size_t)r0 * 1024u + c]       = v0;
            *(float2*)&Ob[(size_t)(r0 + 8) * 1024u + c] = v1;
        }
    }
}

// ---------------- weight transpose + tf32 round ---------------------------
__global__ void transpose_1024(const float* __restrict__ W, float* __restrict__ Wt)
{
    __shared__ float t[32][33];
    const int bx = blockIdx.x * 32, by = blockIdx.y * 32;
    const int tx = threadIdx.x, ty = threadIdx.y;
#pragma unroll
    for (int i = 0; i < 4; i++)
        t[ty + i * 8][tx] = W[(size_t)(by + ty + i * 8) * 1024 + bx + tx];
    __syncthreads();
#pragma unroll
    for (int i = 0; i < 4; i++)
        Wt[(size_t)(bx + ty + i * 8) * 1024 + by + tx] = rna_tf32(t[tx][ty + i * 8]);
}

// ---------------- tf32 rounding copy ---------------------------------------
__global__ void round_copy(const float4* __restrict__ in, float4* __restrict__ out, int n4)
{
    int i = blockIdx.x * blockDim.x + threadIdx.x;
    if (i < n4) {
        float4 v = in[i];
        v.x = rna_tf32(v.x); v.y = rna_tf32(v.y);
        v.z = rna_tf32(v.z); v.w = rna_tf32(v.w);
        out[i] = v;
    }
}

// ---------------- rotary on Q ---------------------------------------------
__global__ void rotary_q_kernel(float* __restrict__ Q, const float* __restrict__ freqs,
                                const int* __restrict__ cur)
{
    const int row = blockIdx.x;
    const int s   = row % SEQn;
    const int p   = threadIdx.x;
    const int col0 = 2*p;
    const int d0   = col0 & 63;

    const int cp = cur[0];
    const int inner = cp % 16;
    const int rs = inner % 4, cs = inner / 4;
    const int fr = rs*16 + (s >> 4), fc = cs*16 + (s & 15);
    const float* f = freqs + ((fr<<6) + fc) * 64;
    const float f0 = f[d0], f1 = f[d0+1];

    float* q = Q + (long long)row*INNERn + col0;
    const float t0 = q[0], t1 = q[1];
    q[0] = t0*cosf(f0) - t1*sinf(f0);
    q[1] = t1*cosf(f1) + t0*sinf(f1);
}

// ---------------- bias + rotary on memory K rows ---------------------------
__global__ void biasrot_k_kernel(float* __restrict__ K, const float* __restrict__ freqs,
                                 const float* __restrict__ rel_table,
                                 const int* __restrict__ memidx,
                                 const int* __restrict__ cur)
{
    const int gid = blockIdx.x;
    const int b = gid / MSn;
    const int j = gid - b*MSn;
    const int m = j >> 8;
    const int jj = j & 255;

    const int p = threadIdx.x;
    const int col0 = 2*p;
    const int h  = col0 >> 6;
    const int d0 = col0 & 63;

    const int cp = cur[0];
    const int ci = cp % 16;
    const int rs = ci % 4, cs = ci / 4, ts = cp / 16;
    const int mi = memidx[m];
    const int mn = mi % 16;
    const int rt = mn % 4, ct = mn / 4, tt = mi / 16;
    const int rel = (rt - rs + 4)*9 + (ct - cs + 4) + (tt - ts + 4)*81;
    const float bias = rel_table[rel*HEADSn + h];

    const int fr = rt*16 + (jj >> 4), fc = ct*16 + (jj & 15);
    const float* f = freqs + ((fr<<6) + fc) * 64;
    const float f0 = f[d0], f1 = f[d0+1];

    float* kp = K + ((long long)b*KVn + j)*INNERn + col0;
    const float t0 = kp[0] + bias, t1 = kp[1] + bias;
    kp[0] = t0*cosf(f0) - t1*sinf(f0);
    kp[1] = t1*cosf(f1) + t0*sinf(f1);
}

// ---------------- host launch ----------------------------------------------
extern "C" void kernel_launch(void* const* d_in, const int* in_sizes, int n_in,
                              void* d_out, int out_size)
{
    const float* x     = (const float*)d_in[0];
    const float* cond  = (const float*)d_in[1];
    const float* freqs = (const float*)d_in[2];
    const float* Wq    = (const float*)d_in[3];
    const float* Wk    = (const float*)d_in[4];
    const float* Wv    = (const float*)d_in[5];
    const float* rel   = (const float*)d_in[6];
    const float* Wo    = (const float*)d_in[7];
    const float* bo    = (const float*)d_in[8];
    const int*   memi  = (const int*)d_in[9];
    const int*   cur   = (const int*)d_in[10];
    float* out = (float*)d_out;

    float *Qb, *Kb, *Vb, *Ob, *Wt, *Xr, *Cr;
    cudaGetSymbolAddress((void**)&Qb, g_Q);
    cudaGetSymbolAddress((void**)&Kb, g_K);
    cudaGetSymbolAddress((void**)&Vb, g_V);
    cudaGetSymbolAddress((void**)&Ob, g_O);
    cudaGetSymbolAddress((void**)&Wt, g_Wt);
    cudaGetSymbolAddress((void**)&Xr, g_Xr);
    cudaGetSymbolAddress((void**)&Cr, g_Cr);

    cudaFuncSetAttribute(flash_attn, cudaFuncAttributeMaxDynamicSharedMemorySize, FL_SMEM);

    float* Wtq = Wt + 0LL * DIMn * INNERn;
    float* Wtk = Wt + 1LL * DIMn * INNERn;
    float* Wtv = Wt + 2LL * DIMn * INNERn;
    float* Wto = Wt + 3LL * DIMn * INNERn;

    // Launch order arranged so launch #5 (ncu -s 5 -c 1) is the big
    // K-projection GEMM, giving real profile data on the dominant kernel.
    // 0,1: rounding copies
    round_copy<<<(ROWS_X*DIMn/4 + 255)/256, 256>>>((const float4*)x,    (float4*)Xr, ROWS_X*DIMn/4);
    round_copy<<<(ROWS_C*DIMn/4 + 255)/256, 256>>>((const float4*)cond, (float4*)Cr, ROWS_C*DIMn/4);
    // 2,3,4: transposes needed before the K gemm
    transpose_1024<<<dim3(32,32), dim3(32,8)>>>(Wq, Wtq);
    transpose_1024<<<dim3(32,32), dim3(32,8)>>>(Wk, Wtk);
    transpose_1024<<<dim3(32,32), dim3(32,8)>>>(Wv, Wtv);
    // 5: K projection (PROFILED)
    gemm_mma<false,false><<<dim3(8, 266), 128>>>(Cr, Wtk, Kb, nullptr, ROWS_C);
    // 6: remaining transpose
    transpose_1024<<<dim3(32,32), dim3(32,8)>>>(Wo, Wto);
    // 7,8: Q and V projections (V rna-rounded for PV mma)
    gemm_mma<false,false><<<dim3(8, 32),  128>>>(Xr, Wtq, Qb, nullptr, ROWS_X);
    gemm_mma<false,true ><<<dim3(8, 266), 128>>>(Cr, Wtv, Vb, nullptr, ROWS_C);

    // 9) rotary(Q)
    rotary_q_kernel<<<ROWS_X, 512>>>(Qb, freqs, cur);

    // 10) bias + rotary on memory K rows
    biasrot_k_kernel<<<Bn*MSn, 512>>>(Kb, freqs, rel, memi, cur);

    // 11) fused flash attention (tf32 mma, online softmax), writes rna(O)
    flash_attn<<<dim3(2, BHn), 256, FL_SMEM>>>(Qb, Kb, Vb, Ob);

    // 12) out = O @ Wo + bo  (tf32 tensor cores, bias epilogue)
    gemm_mma<true,false><<<dim3(8, 32), 128>>>(Ob, Wto, out, bo, ROWS_X);
}

// round 10
// speedup vs baseline: 1.1342x; 1.0228x over previous
#include <cuda_runtime.h>
#include <cstdint>
#include <cstddef>

// ---------------- problem constants (fixed by the dataset) ----------------
#define Bn     16
#define SEQn   256
#define DIMn   1024
#define HEADSn 16
#define DHEADn 64
#define INNERn 1024
#define Mmem   8
#define TXTn   77
#define KVn    (Mmem*SEQn + TXTn)   // 2125
#define MSn    (Mmem*SEQn)          // 2048
#define SCALEf 0.125f               // 64^-0.5

#define ROWS_X   (Bn*SEQn)          // 4096
#define ROWS_C   (Bn*KVn)           // 34000
#define BHn      (Bn*HEADSn)        // 256

// ---------------- scratch (device globals: no allocation allowed) ---------
__device__ float g_Q[ROWS_X * INNERn];
__device__ float g_K[ROWS_C * INNERn];
__device__ float g_V[ROWS_C * INNERn];
__device__ float g_O[ROWS_X * INNERn];
__device__ float g_Wt[4 * DIMn * INNERn];   // [Wtk;Wtv] (2 slots), Wtq, Wto
__device__ float g_Xr[ROWS_X * DIMn];
__device__ float g_Cr[ROWS_C * DIMn];
__device__ float g_cosf[64*64*64];          // cos(freqs), 1MB
__device__ float g_sinf[64*64*64];          // sin(freqs), 1MB

// ---------------- helpers --------------------------------------------------
__device__ __forceinline__ uint32_t smem_u32(const void* p) {
    uint32_t a;
    asm("{ .reg .u64 t; cvta.to.shared.u64 t, %1; cvt.u32.u64 %0, t; }" : "=r"(a) : "l"(p));
    return a;
}
__device__ __forceinline__ float rna_tf32(float x) {
    float y;
    asm("cvt.rna.tf32.f32 %0, %1;" : "=f"(y) : "f"(x));
    return y;
}
#define MMA_TF32(d0,d1,d2,d3,a0,a1,a2,a3,b0,b1)                               \
    asm volatile(                                                             \
        "mma.sync.aligned.m16n8k8.row.col.f32.tf32.tf32.f32 "                 \
        "{%0,%1,%2,%3},{%4,%5,%6,%7},{%8,%9},{%0,%1,%2,%3};"                  \
        : "+f"(d0), "+f"(d1), "+f"(d2), "+f"(d3)                              \
        : "r"(a0), "r"(a1), "r"(a2), "r"(a3), "r"(b0), "r"(b1))
#define CP16(dst, src)     asm volatile("cp.async.cg.shared.global [%0], [%1], 16;" :: "r"(dst), "l"(src))
#define CP16P(dst, src, p) asm volatile("cp.async.cg.shared.global [%0], [%1], 16, %2;" :: "r"(dst), "l"(src), "r"(p))
#define CP_COMMIT()        asm volatile("cp.async.commit_group;" ::: "memory")
#define CP_WAIT(n)         asm volatile("cp.async.wait_group %0;" :: "n"(n) : "memory")

// =================== tf32 mma.sync GEMM (projections) ======================
// C[M,N] = A[M,1024] @ Bt[n][k]^T  (Bt K-major; N = gridDim.x*128)
// Tile 128x128x16, 128 threads, 4 warps 2x2, warp tile 64x64.
// R5-proven 2-stage double-buffer control flow.
// SPLIT: column blocks n0>=1024 write to Cv at (n0-1024) with rna-rounding
// (merged K|V projection).
#define SA_STR 20   // smem row stride in floats (bank-conflict-free)

template<bool BIAS, bool RND, bool SPLIT>
__global__ __launch_bounds__(128, 2)
void gemm_mma(const float* __restrict__ A, const float* __restrict__ Bt,
              float* __restrict__ C, float* __restrict__ Cv,
              const float* __restrict__ bias, int M)
{
    __shared__ float As[2][128 * SA_STR];
    __shared__ float Bs[2][128 * SA_STR];

    const int tid  = threadIdx.x;
    const int wid  = tid >> 5, lane = tid & 31;
    const int g    = lane >> 2, tg = lane & 3;
    const int wm   = (wid >> 1) * 64;   // warp m offset
    const int wn   = (wid & 1) * 64;    // warp n offset
    const int m0   = blockIdx.y * 128, n0 = blockIdx.x * 128;

    float d[4][8][4];
#pragma unroll
    for (int i = 0; i < 4; i++)
#pragma unroll
        for (int j = 0; j < 8; j++)
#pragma unroll
            for (int q = 0; q < 4; q++) d[i][j][q] = 0.f;

    auto issue = [&](int buf, int kt) {
        const int k0 = kt * 16;
#pragma unroll
        for (int e = 0; e < 4; e++) {
            int idx = tid + e * 128;        // 0..511
            int row = idx >> 2, c4 = idx & 3;
            int ga = m0 + row;
            int pa = (ga < M) ? 16 : 0;
            if (ga >= M) ga = M - 1;
            uint32_t da = smem_u32(&As[buf][row * SA_STR + c4 * 4]);
            CP16P(da, A + (size_t)ga * 1024u + k0 + c4 * 4, pa);
            uint32_t db = smem_u32(&Bs[buf][row * SA_STR + c4 * 4]);
            CP16(db, Bt + (size_t)(n0 + row) * 1024u + k0 + c4 * 4);
        }
        CP_COMMIT();
    };

    issue(0, 0);
    issue(1, 1);

    for (int kt = 0; kt < 64; kt++) {
        const int buf = kt & 1;
        if (kt < 63) CP_WAIT(1);
        else         CP_WAIT(0);
        __syncthreads();

#pragma unroll
        for (int ks = 0; ks < 2; ks++) {
            uint32_t af[4][4], bf[8][2];
#pragma unroll
            for (int i = 0; i < 4; i++) {
                const float* base = &As[buf][(wm + i * 16) * SA_STR + ks * 8];
                af[i][0] = __float_as_uint(base[(g)     * SA_STR + tg]);
                af[i][1] = __float_as_uint(base[(g + 8) * SA_STR + tg]);
                af[i][2] = __float_as_uint(base[(g)     * SA_STR + tg + 4]);
                af[i][3] = __float_as_uint(base[(g + 8) * SA_STR + tg + 4]);
            }
#pragma unroll
            for (int j = 0; j < 8; j++) {
                const float* base = &Bs[buf][(wn + j * 8 + g) * SA_STR + ks * 8];
                bf[j][0] = __float_as_uint(base[tg]);
                bf[j][1] = __float_as_uint(base[tg + 4]);
            }
#pragma unroll
            for (int i = 0; i < 4; i++)
#pragma unroll
                for (int j = 0; j < 8; j++)
                    MMA_TF32(d[i][j][0], d[i][j][1], d[i][j][2], d[i][j][3],
                             af[i][0], af[i][1], af[i][2], af[i][3],
                             bf[j][0], bf[j][1]);
        }
        __syncthreads();
        if (kt + 2 < 64) issue(buf, kt + 2);
    }

    // epilogue: warp writes 64x64
    float* Co = C;
    int cb = n0;
    bool dornd = RND;
    if (SPLIT && n0 >= 1024) { Co = Cv; cb = n0 - 1024; dornd = true; }

#pragma unroll
    for (int i = 0; i < 4; i++) {
        const int r0 = m0 + wm + i * 16 + g;
#pragma unroll
        for (int j = 0; j < 8; j++) {
            const int c = cb + wn + j * 8 + tg * 2;
            float2 v0 = make_float2(d[i][j][0], d[i][j][1]);
            float2 v1 = make_float2(d[i][j][2], d[i][j][3]);
            if (BIAS) {
                const float b0 = bias[c], b1 = bias[c + 1];
                v0.x += b0; v0.y += b1; v1.x += b0; v1.y += b1;
            }
            if (dornd) {
                v0.x = rna_tf32(v0.x); v0.y = rna_tf32(v0.y);
                v1.x = rna_tf32(v1.x); v1.y = rna_tf32(v1.y);
            }
            if (r0 < M)     *(float2*)&Co[(size_t)r0 * 1024u + c] = v0;
            if (r0 + 8 < M) *(float2*)&Co[(size_t)(r0 + 8) * 1024u + c] = v1;
        }
    }
}

// =================== fused flash attention (tf32 mma) ======================
// EXACT R5 version (occ 2, per-chunk K+V load then wait(0)).
#define QS_O 0                        // 128 x 68
#define KS_O (QS_O + 128*68)          // 64 x 68
#define VS_O (KS_O + 64*68)           // 64 x 72
#define SS_O (VS_O + 64*72)           // 128 x 68
#define MR_O (SS_O + 128*68)          // 128
#define LR_O (MR_O + 128)             // 128
#define AR_O (LR_O + 128)             // 128
#define FL_SMEM ((AR_O + 128) * 4)    // bytes = 107008

#define NCHUNK ((KVn + 63) / 64)      // 34

__global__ __launch_bounds__(256, 2)
void flash_attn(const float* __restrict__ Q, const float* __restrict__ K,
                const float* __restrict__ V, float* __restrict__ O)
{
    extern __shared__ float sm[];
    const int tid = threadIdx.x;
    const int wid = tid >> 5, lane = tid & 31;
    const int g = lane >> 2, tg = lane & 3;
    const int bh = blockIdx.y, b = bh >> 4, h = bh & 15;
    const int m0 = blockIdx.x * 128;

    const float* Qb = Q + ((size_t)(b * SEQn + m0)) * 1024u + h * 64;
    const float* Kb = K + ((size_t)b * KVn) * 1024u + h * 64;
    const float* Vb = V + ((size_t)b * KVn) * 1024u + h * 64;

    // Q tile: pre-scale + rna-round
    for (int e = tid; e < 128 * 64; e += 256) {
        int r = e >> 6, c = e & 63;
        sm[QS_O + r * 68 + c] = rna_tf32(Qb[(size_t)r * 1024u + c] * SCALEf);
    }
    if (tid < 128) { sm[MR_O + tid] = -1e30f; sm[LR_O + tid] = 0.f; }

    float oacc[4][2][4];
#pragma unroll
    for (int i = 0; i < 4; i++)
#pragma unroll
        for (int j = 0; j < 2; j++)
#pragma unroll
            for (int q = 0; q < 4; q++) oacc[i][j][q] = 0.f;

    const int om = (wid >> 2) * 64;   // warp m offset
    const int on = (wid & 3) * 16;    // warp n offset
    __syncthreads();

    for (int t = 0; t < NCHUNK; t++) {
        const int kv0 = t * 64;
        const int rows = (KVn - kv0 < 64) ? (KVn - kv0) : 64;

        // ---- load K,V chunk (64 x 64 f32 each) via cp.async ----
#pragma unroll
        for (int e = 0; e < 4; e++) {
            int idx = tid + e * 256;          // 0..1023
            int r = idx >> 4, c4 = idx & 15;
            int kvr = kv0 + r; if (kvr >= KVn) kvr = KVn - 1;
            const float* sk = Kb + (size_t)kvr * 1024u + c4 * 4;
            uint32_t dk = smem_u32(&sm[KS_O + r * 68 + c4 * 4]);
            CP16(dk, sk);
            const float* sv = Vb + (size_t)kvr * 1024u + c4 * 4;
            uint32_t dv = smem_u32(&sm[VS_O + r * 72 + c4 * 4]);
            CP16(dv, sv);
        }
        CP_COMMIT();
        CP_WAIT(0);
        __syncthreads();

        // ---- S = Qs @ Ks^T  (warp tile 64x16) ----
        float s[4][2][4];
#pragma unroll
        for (int i = 0; i < 4; i++)
#pragma unroll
            for (int j = 0; j < 2; j++)
#pragma unroll
                for (int q = 0; q < 4; q++) s[i][j][q] = 0.f;

#pragma unroll
        for (int ks = 0; ks < 8; ks++) {
            uint32_t af[4][4], bf[2][2];
#pragma unroll
            for (int i = 0; i < 4; i++) {
                const float* base = &sm[QS_O + (om + i * 16) * 68 + ks * 8];
                af[i][0] = __float_as_uint(base[(g)     * 68 + tg]);
                af[i][1] = __float_as_uint(base[(g + 8) * 68 + tg]);
                af[i][2] = __float_as_uint(base[(g)     * 68 + tg + 4]);
                af[i][3] = __float_as_uint(base[(g + 8) * 68 + tg + 4]);
            }
#pragma unroll
            for (int j = 0; j < 2; j++) {
                const float* base = &sm[KS_O + (on + j * 8 + g) * 68 + ks * 8];
                bf[j][0] = __float_as_uint(base[tg]);
                bf[j][1] = __float_as_uint(base[tg + 4]);
            }
#pragma unroll
            for (int i = 0; i < 4; i++)
#pragma unroll
                for (int j = 0; j < 2; j++)
                    MMA_TF32(s[i][j][0], s[i][j][1], s[i][j][2], s[i][j][3],
                             af[i][0], af[i][1], af[i][2], af[i][3],
                             bf[j][0], bf[j][1]);
        }
        // write S fragments to smem
#pragma unroll
        for (int i = 0; i < 4; i++) {
            const int r0 = om + i * 16 + g;
#pragma unroll
            for (int j = 0; j < 2; j++) {
                const int c = on + j * 8 + tg * 2;
                sm[SS_O + r0 * 68 + c]           = s[i][j][0];
                sm[SS_O + r0 * 68 + c + 1]       = s[i][j][1];
                sm[SS_O + (r0 + 8) * 68 + c]     = s[i][j][2];
                sm[SS_O + (r0 + 8) * 68 + c + 1] = s[i][j][3];
            }
        }
        __syncthreads();

        // ---- online softmax: warp handles rows [wid*16, wid*16+16) ----
#pragma unroll 4
        for (int rr = 0; rr < 16; rr++) {
            const int r = wid * 16 + rr;
            const int c0 = lane * 2;
            float v0 = (c0     < rows) ? sm[SS_O + r * 68 + c0]     : -1e30f;
            float v1 = (c0 + 1 < rows) ? sm[SS_O + r * 68 + c0 + 1] : -1e30f;
            float mx = fmaxf(v0, v1);
#pragma unroll
            for (int o = 16; o; o >>= 1) mx = fmaxf(mx, __shfl_xor_sync(~0u, mx, o));
            const float mold = sm[MR_O + r];
            const float mnew = fmaxf(mold, mx);
            float p0 = (c0     < rows) ? rna_tf32(__expf(v0 - mnew)) : 0.f;
            float p1 = (c0 + 1 < rows) ? rna_tf32(__expf(v1 - mnew)) : 0.f;
            sm[SS_O + r * 68 + c0]     = p0;
            sm[SS_O + r * 68 + c0 + 1] = p1;
            float ls = p0 + p1;
#pragma unroll
            for (int o = 16; o; o >>= 1) ls += __shfl_xor_sync(~0u, ls, o);
            if (lane == 0) {
                const float al = __expf(mold - mnew);
                sm[AR_O + r] = al;
                sm[LR_O + r] = sm[LR_O + r] * al + ls;
                sm[MR_O + r] = mnew;
            }
        }
        __syncthreads();

        // ---- rescale O accumulators ----
#pragma unroll
        for (int i = 0; i < 4; i++) {
            const float a0 = sm[AR_O + om + i * 16 + g];
            const float a1 = sm[AR_O + om + i * 16 + g + 8];
#pragma unroll
            for (int j = 0; j < 2; j++) {
                oacc[i][j][0] *= a0; oacc[i][j][1] *= a0;
                oacc[i][j][2] *= a1; oacc[i][j][3] *= a1;
            }
        }

        // ---- O += P @ V ----
#pragma unroll
        for (int ks = 0; ks < 8; ks++) {
            uint32_t af[4][4], bf[2][2];
#pragma unroll
            for (int i = 0; i < 4; i++) {
                const float* base = &sm[SS_O + (om + i * 16) * 68 + ks * 8];
                af[i][0] = __float_as_uint(base[(g)     * 68 + tg]);
                af[i][1] = __float_as_uint(base[(g + 8) * 68 + tg]);
                af[i][2] = __float_as_uint(base[(g)     * 68 + tg + 4]);
                af[i][3] = __float_as_uint(base[(g + 8) * 68 + tg + 4]);
            }
#pragma unroll
            for (int j = 0; j < 2; j++) {
                bf[j][0] = __float_as_uint(sm[VS_O + (ks * 8 + tg)     * 72 + on + j * 8 + g]);
                bf[j][1] = __float_as_uint(sm[VS_O + (ks * 8 + tg + 4) * 72 + on + j * 8 + g]);
            }
#pragma unroll
            for (int i = 0; i < 4; i++)
#pragma unroll
                for (int j = 0; j < 2; j++)
                    MMA_TF32(oacc[i][j][0], oacc[i][j][1], oacc[i][j][2], oacc[i][j][3],
                             af[i][0], af[i][1], af[i][2], af[i][3],
                             bf[j][0], bf[j][1]);
        }
        __syncthreads();
    }

    // ---- epilogue: O / l, rna-round for out-projection ----
    float* Ob = O + ((size_t)(b * SEQn + m0)) * 1024u + h * 64;
#pragma unroll
    for (int i = 0; i < 4; i++) {
        const int r0 = om + i * 16 + g;
        const float li0 = 1.f / sm[LR_O + r0];
        const float li1 = 1.f / sm[LR_O + r0 + 8];
#pragma unroll
        for (int j = 0; j < 2; j++) {
            const int c = on + j * 8 + tg * 2;
            float2 v0 = make_float2(rna_tf32(oacc[i][j][0] * li0), rna_tf32(oacc[i][j][1] * li0));
            float2 v1 = make_float2(rna_tf32(oacc[i][j][2] * li1), rna_tf32(oacc[i][j][3] * li1));
            *(float2*)&Ob[(size_t)r0 * 1024u + c]       = v0;
            *(float2*)&Ob[(size_t)(r0 + 8) * 1024u + c] = v1;
        }
    }
}

// ---------------- weight transpose + tf32 round ---------------------------
__global__ void transpose_1024(const float* __restrict__ W, float* __restrict__ Wt)
{
    __shared__ float t[32][33];
    const int bx = blockIdx.x * 32, by = blockIdx.y * 32;
    const int tx = threadIdx.x, ty = threadIdx.y;
#pragma unroll
    for (int i = 0; i < 4; i++)
        t[ty + i * 8][tx] = W[(size_t)(by + ty + i * 8) * 1024 + bx + tx];
    __syncthreads();
#pragma unroll
    for (int i = 0; i < 4; i++)
        Wt[(size_t)(bx + ty + i * 8) * 1024 + by + tx] = rna_tf32(t[tx][ty + i * 8]);
}

// ---------------- tf32 rounding copy ---------------------------------------
__global__ void round_copy(const float4* __restrict__ in, float4* __restrict__ out, int n4)
{
    int i = blockIdx.x * blockDim.x + threadIdx.x;
    if (i < n4) {
        float4 v = in[i];
        v.x = rna_tf32(v.x); v.y = rna_tf32(v.y);
        v.z = rna_tf32(v.z); v.w = rna_tf32(v.w);
        out[i] = v;
    }
}

// ---------------- cos/sin tables of freqs ----------------------------------
__global__ void cs_precompute(const float* __restrict__ freqs,
                              float* __restrict__ cf, float* __restrict__ sf)
{
    int i = blockIdx.x * blockDim.x + threadIdx.x;
    if (i < 64*64*64) {
        float v = freqs[i];
        cf[i] = cosf(v);
        sf[i] = sinf(v);
    }
}

// ---------------- rotary on Q (table-driven) -------------------------------
__global__ void rotary_q_kernel(float* __restrict__ Q,
                                const float* __restrict__ cf, const float* __restrict__ sf,
                                const int* __restrict__ cur)
{
    const int row = blockIdx.x;
    const int s   = row % SEQn;
    const int p   = threadIdx.x;
    const int col0 = 2*p;
    const int d0   = col0 & 63;

    const int cp = cur[0];
    const int inner = cp % 16;
    const int rs = inner % 4, cs = inner / 4;
    const int fr = rs*16 + (s >> 4), fc = cs*16 + (s & 15);
    const int fo = ((fr<<6) + fc) * 64 + d0;
    const float c0 = cf[fo], s0 = sf[fo];
    const float c1 = cf[fo+1], s1 = sf[fo+1];

    float* q = Q + (long long)row*INNERn + col0;
    const float t0 = q[0], t1 = q[1];
    q[0] = t0*c0 - t1*s0;
    q[1] = t1*c1 + t0*s1;
}

// ---------------- bias + rotary on memory K rows (table-driven) ------------
__global__ void biasrot_k_kernel(float* __restrict__ K,
                                 const float* __restrict__ cf, const float* __restrict__ sf,
                                 const float* __restrict__ rel_table,
                                 const int* __restrict__ memidx,
                                 const int* __restrict__ cur)
{
    const int gid = blockIdx.x;
    const int b = gid / MSn;
    const int j = gid - b*MSn;
    const int m = j >> 8;
    const int jj = j & 255;

    const int p = threadIdx.x;
    const int col0 = 2*p;
    const int h  = col0 >> 6;
    const int d0 = col0 & 63;

    const int cp = cur[0];
    const int ci = cp % 16;
    const int rs = ci % 4, cs = ci / 4, ts = cp / 16;
    const int mi = memidx[m];
    const int mn = mi % 16;
    const int rt = mn % 4, ct = mn / 4, tt = mi / 16;
    const int rel = (rt - rs + 4)*9 + (ct - cs + 4) + (tt - ts + 4)*81;
    const float bias = rel_table[rel*HEADSn + h];

    const int fr = rt*16 + (jj >> 4), fc = ct*16 + (jj & 15);
    const int fo = ((fr<<6) + fc) * 64 + d0;
    const float c0 = cf[fo], s0 = sf[fo];
    const float c1 = cf[fo+1], s1 = sf[fo+1];

    float* kp = K + ((long long)b*KVn + j)*INNERn + col0;
    const float t0 = kp[0] + bias, t1 = kp[1] + bias;
    kp[0] = t0*c0 - t1*s0;
    kp[1] = t1*c1 + t0*s1;
}

// ---------------- host launch ----------------------------------------------
extern "C" void kernel_launch(void* const* d_in, const int* in_sizes, int n_in,
                              void* d_out, int out_size)
{
    const float* x     = (const float*)d_in[0];
    const float* cond  = (const float*)d_in[1];
    const float* freqs = (const float*)d_in[2];
    const float* Wq    = (const float*)d_in[3];
    const float* Wk    = (const float*)d_in[4];
    const float* Wv    = (const float*)d_in[5];
    const float* rel   = (const float*)d_in[6];
    const float* Wo    = (const float*)d_in[7];
    const float* bo    = (const float*)d_in[8];
    const int*   memi  = (const int*)d_in[9];
    const int*   cur   = (const int*)d_in[10];
    float* out = (float*)d_out;

    float *Qb, *Kb, *Vb, *Ob, *Wt, *Xr, *Cr, *Cf, *Sf;
    cudaGetSymbolAddress((void**)&Qb, g_Q);
    cudaGetSymbolAddress((void**)&Kb, g_K);
    cudaGetSymbolAddress((void**)&Vb, g_V);
    cudaGetSymbolAddress((void**)&Ob, g_O);
    cudaGetSymbolAddress((void**)&Wt, g_Wt);
    cudaGetSymbolAddress((void**)&Xr, g_Xr);
    cudaGetSymbolAddress((void**)&Cr, g_Cr);
    cudaGetSymbolAddress((void**)&Cf, g_cosf);
    cudaGetSymbolAddress((void**)&Sf, g_sinf);

    cudaFuncSetAttribute(flash_attn, cudaFuncAttributeMaxDynamicSharedMemorySize, FL_SMEM);

    // Wt layout: [Wtk (rows 0-1023); Wtv (rows 1024-2047)] | Wtq | Wto
    float* Wtkv = Wt;                               // 2048 x 1024
    float* Wtq  = Wt + 2LL * DIMn * INNERn;
    float* Wto  = Wt + 3LL * DIMn * INNERn;

    // prep: rounding copies, weight transposes, trig tables
    round_copy<<<(ROWS_X*DIMn/4 + 255)/256, 256>>>((const float4*)x,    (float4*)Xr, ROWS_X*DIMn/4);
    round_copy<<<(ROWS_C*DIMn/4 + 255)/256, 256>>>((const float4*)cond, (float4*)Cr, ROWS_C*DIMn/4);
    transpose_1024<<<dim3(32,32), dim3(32,8)>>>(Wk, Wtkv);
    transpose_1024<<<dim3(32,32), dim3(32,8)>>>(Wv, Wtkv + (size_t)DIMn * INNERn);
    cs_precompute<<<(64*64*64 + 255)/256, 256>>>(freqs, Cf, Sf);
    // merged K|V projection (N=2048): K cols 0-1023 (raw), V cols 1024-2047 (rna)
    gemm_mma<false,false,true><<<dim3(16, 266), 128>>>(Cr, Wtkv, Kb, Vb, nullptr, ROWS_C);
    transpose_1024<<<dim3(32,32), dim3(32,8)>>>(Wq, Wtq);
    transpose_1024<<<dim3(32,32), dim3(32,8)>>>(Wo, Wto);
    // Q projection
    gemm_mma<false,false,false><<<dim3(8, 32), 128>>>(Xr, Wtq, Qb, nullptr, nullptr, ROWS_X);

    // rotary(Q), bias+rotary(K-mem) — table-driven
    rotary_q_kernel<<<ROWS_X, 512>>>(Qb, Cf, Sf, cur);
    biasrot_k_kernel<<<Bn*MSn, 512>>>(Kb, Cf, Sf, rel, memi, cur);

    // fused flash attention (tf32 mma, online softmax), writes rna(O)
    flash_attn<<<dim3(2, BHn), 256, FL_SMEM>>>(Qb, Kb, Vb, Ob);

    // out = O @ Wo + bo
    gemm_mma<true,false,false><<<dim3(8, 32), 128>>>(Ob, Wto, out, nullptr, bo, ROWS_X);
}